// round 4
// baseline (speedup 1.0000x reference)
#include <cuda_runtime.h>
#include <math.h>

#define Nn 20000
#define Ee 320000
#define ET (Ee + Nn)
#define Bb 128
#define IN_F 25
#define D 64
#define HD 8
#define HDD (HD * D) /* 512 */

// ---------------- scratch (static device globals; no allocation) ----------------
__device__ float g_h0[Nn * D];          // 5.1 MB
__device__ float g_xh[Nn * HDD];        // 41 MB
__device__ float g_as[Nn * HD];
__device__ float g_ad[Nn * HD];
__device__ int   g_cnt[Nn];
__device__ int   g_off[Nn + 1];
__device__ int   g_cur[Nn];
__device__ int   g_esrc[ET];
__device__ float g_agg[Nn * HDD];       // 41 MB
__device__ float g_outF[Nn * D];        // 5.1 MB
__device__ int   g_gstart[Bb];
__device__ int   g_gcnt[Bb];
__device__ float g_w2[Nn];
__device__ float g_hS[Bb * D];
__device__ float g_cS[Bb * D];
__device__ float g_q[Bb * D];
__device__ float g_qstar[Bb * 2 * D];
// index dtype handling
__device__ int   g_is64;
__device__ int   g_eidx[2 * Ee];        // converted edge_index (int32)
__device__ int   g_bat[Nn];             // converted batch (int32)

__device__ __forceinline__ float sigf(float x) { return 1.0f / (1.0f + __expf(-x)); }

// ---------------- dtype probe: int64 values in [0,20000) have hi word == 0 ------
__global__ void k_detect(const void* __restrict__ ei) {
    if (threadIdx.x == 0) {
        const int2* p = (const int2*)ei;
        int ok64 = 1;
        for (int j = 0; j < 64; j++) if (p[j].y != 0) ok64 = 0;
        g_is64 = ok64;
    }
}

// ---------------- convert indices to int32 --------------------------------------
__global__ void k_cvt(const void* __restrict__ ei, const void* __restrict__ bat) {
    int i = blockIdx.x * blockDim.x + threadIdx.x;
    int is64 = g_is64;
    if (i < 2 * Ee)
        g_eidx[i] = is64 ? (int)((const long long*)ei)[i] : ((const int*)ei)[i];
    if (i < Nn)
        g_bat[i] = is64 ? (int)((const long long*)bat)[i] : ((const int*)bat)[i];
}

// ---------------- init (must run every launch: graph replays mutate state) ------
__global__ void k_init() {
    int i = blockIdx.x * blockDim.x + threadIdx.x;
    if (i < Nn) g_cnt[i] = 0;
    if (i < Bb) { g_gstart[i] = Nn; g_gcnt[i] = 0; }
    if (i < Bb * D) { g_hS[i] = 0.f; g_cS[i] = 0.f; }
    if (i < Bb * 2 * D) g_qstar[i] = 0.f;
}

// ---------------- h0 = relu(x @ W0 + b0) ----------------------------------------
__global__ void k_h0(const float* __restrict__ x, const float* __restrict__ W0,
                     const float* __restrict__ b0) {
    __shared__ __align__(16) float sW[IN_F * D];
    __shared__ __align__(16) float sx[4][IN_F];
    int tid = threadIdx.x;
    for (int i = tid; i < IN_F * D; i += 256) sW[i] = W0[i];
    int r0 = blockIdx.x * 4;
    for (int i = tid; i < 4 * IN_F; i += 256) {
        int r = i / IN_F, k = i % IN_F;
        sx[r][k] = x[(r0 + r) * IN_F + k];
    }
    __syncthreads();
    int r = tid >> 6, c = tid & 63;
    float acc = b0[c];
#pragma unroll
    for (int k = 0; k < IN_F; k++) acc += sx[r][k] * sW[k * D + c];
    g_h0[(r0 + r) * D + c] = fmaxf(acc, 0.f);
}

// ---------------- xh = h0 @ Wg  ([20000,64]@[64,512]) ---------------------------
__global__ void k_xh(const float* __restrict__ Wg) {
    __shared__ __align__(16) float sh[16][D];
    int tid = threadIdx.x;
    int r0 = blockIdx.x * 16;
    {
        const float4* src = (const float4*)(g_h0 + r0 * D);
        float4* dstS = (float4*)&sh[0][0];
        for (int i = tid; i < 16 * D / 4; i += 256) dstS[i] = src[i];
    }
    __syncthreads();
    float acc0[16], acc1[16];
#pragma unroll
    for (int r = 0; r < 16; r++) { acc0[r] = 0.f; acc1[r] = 0.f; }
    int c0 = tid, c1 = tid + 256;
    for (int k = 0; k < D; k++) {
        float w0 = Wg[k * HDD + c0];
        float w1 = Wg[k * HDD + c1];
#pragma unroll
        for (int r = 0; r < 16; r++) {
            float a = sh[r][k];
            acc0[r] += a * w0;
            acc1[r] += a * w1;
        }
    }
#pragma unroll
    for (int r = 0; r < 16; r++) {
        g_xh[(r0 + r) * HDD + c0] = acc0[r];
        g_xh[(r0 + r) * HDD + c1] = acc1[r];
    }
}

// ---------------- a_s, a_d ------------------------------------------------------
__global__ void k_att(const float* __restrict__ att_src, const float* __restrict__ att_dst) {
    int i = blockIdx.x * blockDim.x + threadIdx.x;  // i = n*8 + h
    if (i >= Nn * HD) return;
    int h = i & 7;
    const float4* xr = (const float4*)(g_xh + i * D);
    const float4* a4 = (const float4*)(att_src + h * D);
    const float4* b4 = (const float4*)(att_dst + h * D);
    float s = 0.f, d = 0.f;
#pragma unroll
    for (int j = 0; j < 16; j++) {
        float4 v = xr[j], a = a4[j], b = b4[j];
        s += v.x * a.x + v.y * a.y + v.z * a.z + v.w * a.w;
        d += v.x * b.x + v.y * b.y + v.z * b.z + v.w * b.w;
    }
    g_as[i] = s;
    g_ad[i] = d;
}

// ---------------- CSR build: histogram / scan / scatter -------------------------
__global__ void k_hist() {
    int e = blockIdx.x * blockDim.x + threadIdx.x;
    if (e < ET) {
        int dst = (e < Ee) ? g_eidx[Ee + e] : (e - Ee);
        atomicAdd(&g_cnt[dst], 1);
    }
    if (e < Nn) {
        int b = g_bat[e];
        atomicMin(&g_gstart[b], e);
        atomicAdd(&g_gcnt[b], 1);
    }
}

__global__ void k_scan() {
    __shared__ int sv[1024];
    __shared__ int s_run;
    int tid = threadIdx.x;
    if (tid == 0) s_run = 0;
    __syncthreads();
    for (int base = 0; base < Nn; base += 1024) {
        int idx = base + tid;
        int v = (idx < Nn) ? g_cnt[idx] : 0;
        sv[tid] = v;
        __syncthreads();
        for (int off = 1; off < 1024; off <<= 1) {
            int t = (tid >= off) ? sv[tid - off] : 0;
            __syncthreads();
            sv[tid] += t;
            __syncthreads();
        }
        int incl = sv[tid];
        int run = s_run;
        if (idx < Nn) {
            int ex = run + incl - v;
            g_off[idx] = ex;
            g_cur[idx] = ex;
        }
        __syncthreads();
        if (tid == 1023) s_run = run + sv[1023];
        __syncthreads();
    }
    if (tid == 0) g_off[Nn] = s_run;
}

__global__ void k_scatter() {
    int e = blockIdx.x * blockDim.x + threadIdx.x;
    if (e >= ET) return;
    int src, dst;
    if (e < Ee) { src = g_eidx[e]; dst = g_eidx[Ee + e]; }
    else        { src = e - Ee;    dst = src; }
    int p = atomicAdd(&g_cur[dst], 1);
    g_esrc[p] = src;
}

// ---------------- fused per-dst segment softmax + aggregation -------------------
// warp per dst node. lane -> head h = lane>>2, columns [lane*16, lane*16+16)
#define FMA4(A, R) { A.x += w * R.x; A.y += w * R.y; A.z += w * R.z; A.w += w * R.w; }
__global__ void k_agg() {
    int warp = (blockIdx.x * blockDim.x + threadIdx.x) >> 5;
    int lane = threadIdx.x & 31;
    if (warp >= Nn) return;
    int v = warp;
    int beg = g_off[v], end = g_off[v + 1];
    int h = lane >> 2;
    float adh = g_ad[v * HD + h];

    float mx = -1e30f;
    for (int i = beg; i < end; i++) {
        int s = g_esrc[i];
        float e = g_as[s * HD + h] + adh;
        e = (e > 0.f) ? e : 0.2f * e;
        mx = fmaxf(mx, e);
    }
    float ssum = 0.f;
    float4 a0 = {0, 0, 0, 0}, a1 = {0, 0, 0, 0}, a2 = {0, 0, 0, 0}, a3 = {0, 0, 0, 0};
    for (int i = beg; i < end; i++) {
        int s = g_esrc[i];
        float e = g_as[s * HD + h] + adh;
        e = (e > 0.f) ? e : 0.2f * e;
        float w = __expf(e - mx);
        ssum += w;
        const float4* row = (const float4*)(g_xh + s * HDD) + lane * 4;
        float4 r0 = row[0], r1 = row[1], r2 = row[2], r3 = row[3];
        FMA4(a0, r0); FMA4(a1, r1); FMA4(a2, r2); FMA4(a3, r3);
    }
    float inv = 1.f / ssum;
    float4* o = (float4*)(g_agg + v * HDD) + lane * 4;
    o[0] = make_float4(a0.x * inv, a0.y * inv, a0.z * inv, a0.w * inv);
    o[1] = make_float4(a1.x * inv, a1.y * inv, a1.z * inv, a1.w * inv);
    o[2] = make_float4(a2.x * inv, a2.y * inv, a2.z * inv, a2.w * inv);
    o[3] = make_float4(a3.x * inv, a3.y * inv, a3.z * inv, a3.w * inv);
}

// ---------------- out = relu(relu(agg + bg) @ Wh + bh) --------------------------
__global__ void k_out(const float* __restrict__ bg, const float* __restrict__ Wh,
                      const float* __restrict__ bh) {
    __shared__ __align__(16) float sA[16 * HDD];  // 32 KB
    int tid = threadIdx.x;
    int r0 = blockIdx.x * 16;
    const float4* src = (const float4*)(g_agg + r0 * HDD);
    const float4* bg4 = (const float4*)bg;
    float4* dstS = (float4*)sA;
    for (int i = tid; i < 16 * HDD / 4; i += 256) {
        float4 a = src[i];
        float4 b = bg4[i & 127];
        a.x = fmaxf(a.x + b.x, 0.f); a.y = fmaxf(a.y + b.y, 0.f);
        a.z = fmaxf(a.z + b.z, 0.f); a.w = fmaxf(a.w + b.w, 0.f);
        dstS[i] = a;
    }
    __syncthreads();
    int c = tid & 63, rg = tid >> 6;
    float acc[4] = {0.f, 0.f, 0.f, 0.f};
    for (int k = 0; k < HDD; k += 4) {
        float w0 = Wh[(k + 0) * D + c];
        float w1 = Wh[(k + 1) * D + c];
        float w2 = Wh[(k + 2) * D + c];
        float w3 = Wh[(k + 3) * D + c];
#pragma unroll
        for (int r = 0; r < 4; r++) {
            float4 a = *(const float4*)&sA[(rg * 4 + r) * HDD + k];
            acc[r] += a.x * w0 + a.y * w1 + a.z * w2 + a.w * w3;
        }
    }
    float bhc = bh[c];
#pragma unroll
    for (int r = 0; r < 4; r++)
        g_outF[(r0 + rg * 4 + r) * D + c] = fmaxf(acc[r] + bhc, 0.f);
}

// ---------------- Set2Set LSTM cell ---------------------------------------------
__global__ void k_lstm(const float* __restrict__ W_ih, const float* __restrict__ W_hh,
                       const float* __restrict__ b_ih, const float* __restrict__ b_hh) {
    __shared__ __align__(16) float sqs[2 * D];
    __shared__ __align__(16) float shh[D];
    __shared__ __align__(16) float sg[4 * D];
    int b = blockIdx.x, tid = threadIdx.x;
    if (tid < 2 * D) sqs[tid] = g_qstar[b * 2 * D + tid];
    if (tid < D) shh[tid] = g_hS[b * D + tid];
    __syncthreads();
    int j = tid;
    float acc = b_ih[j] + b_hh[j];
    const float4* wi = (const float4*)(W_ih + j * 2 * D);
#pragma unroll
    for (int k = 0; k < 2 * D / 4; k++) {
        float4 w = wi[k];
        acc += w.x * sqs[4 * k] + w.y * sqs[4 * k + 1] + w.z * sqs[4 * k + 2] + w.w * sqs[4 * k + 3];
    }
    const float4* wh = (const float4*)(W_hh + j * D);
#pragma unroll
    for (int k = 0; k < D / 4; k++) {
        float4 w = wh[k];
        acc += w.x * shh[4 * k] + w.y * shh[4 * k + 1] + w.z * shh[4 * k + 2] + w.w * shh[4 * k + 3];
    }
    sg[j] = acc;
    __syncthreads();
    if (tid < D) {
        float ig = sg[tid], fg = sg[D + tid], gg = sg[2 * D + tid], og = sg[3 * D + tid];
        float c = sigf(fg) * g_cS[b * D + tid] + sigf(ig) * tanhf(gg);
        float hh = sigf(og) * tanhf(c);
        g_cS[b * D + tid] = c;
        g_hS[b * D + tid] = hh;
        g_q[b * D + tid] = hh;
    }
}

// ---------------- Set2Set fused attention (batch is sorted -> contiguous segs) --
__global__ void k_s2s_attn() {
    __shared__ __align__(16) float sq[D];
    __shared__ __align__(16) float red[256];
    int b = blockIdx.x, tid = threadIdx.x;
    if (tid < D) sq[tid] = g_q[b * D + tid];
    __syncthreads();
    int start = g_gstart[b], cnt = g_gcnt[b];

    // pass 1: e2 + max
    float lm = -3.0e38f;
    for (int i = tid; i < cnt; i += 256) {
        int n = start + i;
        const float4* orow = (const float4*)(g_outF + n * D);
        const float4* q4 = (const float4*)sq;
        float e = 0.f;
#pragma unroll
        for (int j = 0; j < 16; j++) {
            float4 o = orow[j], qv = q4[j];
            e += o.x * qv.x + o.y * qv.y + o.z * qv.z + o.w * qv.w;
        }
        g_w2[n] = e;
        lm = fmaxf(lm, e);
    }
    red[tid] = lm;
    __syncthreads();
    for (int o = 128; o > 0; o >>= 1) {
        if (tid < o) red[tid] = fmaxf(red[tid], red[tid + o]);
        __syncthreads();
    }
    float m2 = red[0];
    __syncthreads();

    // pass 2: w = exp(e - m2), sum
    float ls = 0.f;
    for (int i = tid; i < cnt; i += 256) {
        int n = start + i;
        float w = __expf(g_w2[n] - m2);
        g_w2[n] = w;
        ls += w;
    }
    red[tid] = ls;
    __syncthreads();
    for (int o = 128; o > 0; o >>= 1) {
        if (tid < o) red[tid] += red[tid + o];
        __syncthreads();
    }
    float s2 = red[0];
    __syncthreads();

    // pass 3: r = sum(w * out) / s2 ; write q_star = [q, r]
    int c = tid & 63, g = tid >> 6;
    float racc = 0.f;
    for (int i = g; i < cnt; i += 4) {
        int n = start + i;
        racc += g_w2[n] * g_outF[n * D + c];
    }
    red[tid] = racc;
    __syncthreads();
    if (tid < 64) {
        float r = red[tid] + red[64 + tid] + red[128 + tid] + red[192 + tid];
        r = (cnt > 0) ? r / s2 : 0.f;
        g_qstar[b * 2 * D + D + tid] = r;
        g_qstar[b * 2 * D + tid] = sq[tid];
    }
}

// ---------------- final MLP: y = relu(q_star @ W1 + b1) @ W2 + b2 ---------------
__global__ void k_fin(const float* __restrict__ W1, const float* __restrict__ b1,
                      const float* __restrict__ W2, const float* __restrict__ b2,
                      float* __restrict__ out) {
    __shared__ __align__(16) float sqs[2 * D];
    __shared__ __align__(16) float red[64];
    int b = blockIdx.x, tid = threadIdx.x;
    sqs[tid] = g_qstar[b * 2 * D + tid];
    sqs[D + tid] = g_qstar[b * 2 * D + D + tid];
    __syncthreads();
    float acc = b1[tid];
    for (int k = 0; k < 2 * D; k++) acc += sqs[k] * W1[k * D + tid];
    acc = fmaxf(acc, 0.f);
    red[tid] = acc * W2[tid];
    __syncthreads();
    for (int o = 32; o > 0; o >>= 1) {
        if (tid < o) red[tid] += red[tid + o];
        __syncthreads();
    }
    if (tid == 0) out[b] = red[0] + b2[0];
}

// ---------------- launch --------------------------------------------------------
extern "C" void kernel_launch(void* const* d_in, const int* in_sizes, int n_in,
                              void* d_out, int out_size) {
    const float* x        = (const float*)d_in[0];
    const void*  ei       = d_in[1];
    const void*  bat      = d_in[2];
    const float* W0       = (const float*)d_in[3];
    const float* b0       = (const float*)d_in[4];
    const float* Wg       = (const float*)d_in[5];
    const float* att_src  = (const float*)d_in[6];
    const float* att_dst  = (const float*)d_in[7];
    const float* bg       = (const float*)d_in[8];
    const float* Wh       = (const float*)d_in[9];
    const float* bh       = (const float*)d_in[10];
    const float* W_ih     = (const float*)d_in[11];
    const float* W_hh     = (const float*)d_in[12];
    const float* b_ih     = (const float*)d_in[13];
    const float* b_hh     = (const float*)d_in[14];
    const float* W1       = (const float*)d_in[15];
    const float* b1       = (const float*)d_in[16];
    const float* W2       = (const float*)d_in[17];
    const float* b2       = (const float*)d_in[18];
    float* out            = (float*)d_out;

    k_detect<<<1, 32>>>(ei);
    k_cvt<<<(2 * Ee + 255) / 256, 256>>>(ei, bat);
    k_init<<<(Nn + 255) / 256, 256>>>();
    k_h0<<<Nn / 4, 256>>>(x, W0, b0);
    k_xh<<<Nn / 16, 256>>>(Wg);
    k_att<<<(Nn * HD + 255) / 256, 256>>>(att_src, att_dst);
    k_hist<<<(ET + 255) / 256, 256>>>();
    k_scan<<<1, 1024>>>();
    k_scatter<<<(ET + 255) / 256, 256>>>();
    k_agg<<<Nn / 8, 256>>>();
    k_out<<<Nn / 16, 256>>>(bg, Wh, bh);
    for (int it = 0; it < 3; it++) {
        k_lstm<<<Bb, 256>>>(W_ih, W_hh, b_ih, b_hh);
        k_s2s_attn<<<Bb, 256>>>();
    }
    k_fin<<<Bb, 64>>>(W1, b1, W2, b2, out);
}